// round 15
// baseline (speedup 1.0000x reference)
#include <cuda_runtime.h>
#include <cuda_fp16.h>

#define NN   50000
#define EE   800000
#define HID  128
#define BK   64          // padded bucket width (max degree incl. self-loop ~40)
#define ATTN_BLOCKS 592  // 4 blocks/SM x 148 SMs, one wave, persistent warps

// ---------------- device scratch (no allocations allowed) ----------------
__device__ float  d_h1[NN * HID];    // x @ W1 (fp32)
__device__ float  d_t1[NN * HID];    // relu(layer1 out)
__device__ float  d_h2[NN * HID];    // t1 @ W2 (fp32)
__device__ __half d_hh[NN * HID];    // fp16 gather copy of current layer's h
__device__ float  d_al[NN];
__device__ float  d_ar[NN];
__device__ int    d_srcPad[NN * BK]; // padded per-dst source buckets
__device__ int    d_fill[NN];        // per-dst degree (incl. self-loop)
__device__ float  d_p[NN * 8];       // per-node [p_src(4), p_dst(4)]

// ---------------- packed f32x2 helpers (sm_100+ FFMA2 path) ----------------
__device__ __forceinline__ unsigned long long pack2(float lo, float hi) {
    unsigned long long r;
    asm("mov.b64 %0,{%1,%2};" : "=l"(r) : "f"(lo), "f"(hi));
    return r;
}
__device__ __forceinline__ unsigned long long fma2(unsigned long long a,
                                                   unsigned long long b,
                                                   unsigned long long c) {
    unsigned long long d;
    asm("fma.rn.f32x2 %0,%1,%2,%3;" : "=l"(d) : "l"(a), "l"(b), "l"(c));
    return d;
}
__device__ __forceinline__ unsigned long long mul2(unsigned long long a,
                                                   unsigned long long b) {
    unsigned long long d;
    asm("mul.rn.f32x2 %0,%1,%2;" : "=l"(d) : "l"(a), "l"(b));
    return d;
}
__device__ __forceinline__ void unpack2(unsigned long long v, float& lo, float& hi) {
    asm("mov.b64 {%0,%1},%2;" : "=f"(lo), "=f"(hi) : "l"(v));
}

// convert uint4 (8 fp16) -> 4 packed f32x2
__device__ __forceinline__ void cvt8p(uint4 r, unsigned long long* o) {
    float2 a = __half22float2(*reinterpret_cast<__half2*>(&r.x));
    float2 b = __half22float2(*reinterpret_cast<__half2*>(&r.y));
    float2 c = __half22float2(*reinterpret_cast<__half2*>(&r.z));
    float2 d = __half22float2(*reinterpret_cast<__half2*>(&r.w));
    o[0] = pack2(a.x, a.y); o[1] = pack2(b.x, b.y);
    o[2] = pack2(c.x, c.y); o[3] = pack2(d.x, d.y);
}

// ---------------- scan-free CSR: padded bucket scatter ----------------
__global__ void k_place1(const int* __restrict__ ei) {
    int e = blockIdx.x * blockDim.x + threadIdx.x;
    if (e >= EE) return;
    int c = ei[EE + e];
    int pos = atomicAdd(&d_fill[c], 1);
    if (pos < BK) d_srcPad[c * BK + pos] = ei[e];
}
__global__ void k_place2() {
    int n = blockIdx.x * blockDim.x + threadIdx.x;
    if (n >= NN) return;
    int pos = atomicAdd(&d_fill[n], 1);
    if (pos < BK) d_srcPad[n * BK + pos] = n;
}

// ---------------- GEMM: C[M,128] = A[M,128] @ B[128,128], fp32 via FFMA2 (R9 proven) ----------------
__global__ void __launch_bounds__(256) k_gemm(const float* __restrict__ Aext,
                                              const float* __restrict__ B,
                                              const float* __restrict__ attl,
                                              const float* __restrict__ attr,
                                              int selA, int selC) {
    const float* A = selA ? d_t1 : Aext;
    float* C = selC ? d_h2 : d_h1;

    __shared__ float As[16][132];
    __shared__ float Bs[16][128];

    int tid = threadIdx.x;
    int tr = tid >> 4, tc = tid & 15;
    int mBase = blockIdx.x * 128;
    int c0 = tc * 4;
    int c1 = 64 + tc * 4;

    unsigned long long acc[8][4];
    unsigned long long z = pack2(0.f, 0.f);
    #pragma unroll
    for (int i = 0; i < 8; i++)
        #pragma unroll
        for (int p = 0; p < 4; p++) acc[i][p] = z;

    for (int kc = 0; kc < 128; kc += 16) {
        #pragma unroll
        for (int l = 0; l < 2; l++) {
            int f = tid + l * 256;
            int r = f >> 2, cg = (f & 3) << 2;
            float4 v = make_float4(0.f, 0.f, 0.f, 0.f);
            int gr = mBase + r;
            if (gr < NN) v = *reinterpret_cast<const float4*>(A + (size_t)gr * HID + kc + cg);
            As[cg + 0][r] = v.x; As[cg + 1][r] = v.y; As[cg + 2][r] = v.z; As[cg + 3][r] = v.w;
            int k = f >> 5, n4 = (f & 31) << 2;
            *reinterpret_cast<float4*>(&Bs[k][n4]) =
                *reinterpret_cast<const float4*>(B + (size_t)(kc + k) * HID + n4);
        }
        __syncthreads();
        #pragma unroll
        for (int kk = 0; kk < 16; kk++) {
            float4 a0 = *reinterpret_cast<const float4*>(&As[kk][tr * 8]);
            float4 a1 = *reinterpret_cast<const float4*>(&As[kk][tr * 8 + 4]);
            float4 b0 = *reinterpret_cast<const float4*>(&Bs[kk][c0]);
            float4 b1 = *reinterpret_cast<const float4*>(&Bs[kk][c1]);
            unsigned long long pb[4];
            pb[0] = pack2(b0.x, b0.y); pb[1] = pack2(b0.z, b0.w);
            pb[2] = pack2(b1.x, b1.y); pb[3] = pack2(b1.z, b1.w);
            float av[8] = {a0.x, a0.y, a0.z, a0.w, a1.x, a1.y, a1.z, a1.w};
            #pragma unroll
            for (int i = 0; i < 8; i++) {
                unsigned long long ad = pack2(av[i], av[i]);
                #pragma unroll
                for (int p = 0; p < 4; p++) acc[i][p] = fma2(ad, pb[p], acc[i][p]);
            }
        }
        __syncthreads();
    }

    float alv[8], arv[8];
    #pragma unroll
    for (int j = 0; j < 4; j++) {
        alv[j]     = attl[c0 + j]; arv[j]     = attr[c0 + j];
        alv[4 + j] = attl[c1 + j]; arv[4 + j] = attr[c1 + j];
    }

    #pragma unroll
    for (int i = 0; i < 8; i++) {
        int gr = mBase + tr * 8 + i;
        float cv[8];
        unpack2(acc[i][0], cv[0], cv[1]); unpack2(acc[i][1], cv[2], cv[3]);
        unpack2(acc[i][2], cv[4], cv[5]); unpack2(acc[i][3], cv[6], cv[7]);
        float pl = 0.f, pr = 0.f;
        #pragma unroll
        for (int j = 0; j < 8; j++) { pl += cv[j] * alv[j]; pr += cv[j] * arv[j]; }
        #pragma unroll
        for (int off = 8; off; off >>= 1) {
            pl += __shfl_xor_sync(0xffffffffu, pl, off);
            pr += __shfl_xor_sync(0xffffffffu, pr, off);
        }
        if (gr < NN) {
            *reinterpret_cast<float4*>(C + (size_t)gr * HID + c0) =
                make_float4(cv[0], cv[1], cv[2], cv[3]);
            *reinterpret_cast<float4*>(C + (size_t)gr * HID + c1) =
                make_float4(cv[4], cv[5], cv[6], cv[7]);
            __half2 p01 = __floats2half2_rn(cv[0], cv[1]);
            __half2 p23 = __floats2half2_rn(cv[2], cv[3]);
            __half2 p45 = __floats2half2_rn(cv[4], cv[5]);
            __half2 p67 = __floats2half2_rn(cv[6], cv[7]);
            uint2 u0, u1;
            u0.x = *reinterpret_cast<unsigned*>(&p01); u0.y = *reinterpret_cast<unsigned*>(&p23);
            u1.x = *reinterpret_cast<unsigned*>(&p45); u1.y = *reinterpret_cast<unsigned*>(&p67);
            *reinterpret_cast<uint2*>(d_hh + (size_t)gr * HID + c0) = u0;
            *reinterpret_cast<uint2*>(d_hh + (size_t)gr * HID + c1) = u1;
            if (tc == 0) { d_al[gr] = pl; d_ar[gr] = pr; }
        }
    }
}

// ---------------- fused SuperGAT attention ----------------
// Persistent grid-stride warps; 16-lane x 2-edge layout; no-max softmax;
// FFMA2 packed dot + accumulate; 32-bit addressing.
__global__ void __launch_bounds__(256) k_attn(int selH, const float* __restrict__ bias,
                                              int doRelu, int doProj,
                                              const float* __restrict__ Wc) {
    int lane = threadIdx.x & 31;
    int g = lane >> 4, f = lane & 15;
    int warpGlobal = (blockIdx.x * blockDim.x + threadIdx.x) >> 5;
    const int warpStride = ATTN_BLOCKS * (256 / 32);
    const float* h = selH ? d_h2 : d_h1;
    const __half* hh = d_hh;

    // per-lane constants hoisted out of the node loop
    float4 bv0, bv1;
    {
        const float4* bb = reinterpret_cast<const float4*>(bias + f * 8);
        bv0 = bb[0]; bv1 = bb[1];
    }

    for (int gw = warpGlobal; gw < NN; gw += warpStride) {
        unsigned rowOff = (unsigned)gw * HID + ((unsigned)f << 3);
        unsigned long long hdp[4];
        {
            const float4* hr = reinterpret_cast<const float4*>(h + rowOff);
            float4 x0 = hr[0], x1 = hr[1];
            hdp[0] = pack2(x0.x, x0.y); hdp[1] = pack2(x0.z, x0.w);
            hdp[2] = pack2(x1.x, x1.y); hdp[3] = pack2(x1.z, x1.w);
        }
        float ard = d_ar[gw];
        const int* sp = d_srcPad + gw * BK;
        int deg = d_fill[gw];
        if (deg > BK) deg = BK;

        unsigned long long accp[4];
        unsigned long long z = pack2(0.f, 0.f);
        accp[0] = z; accp[1] = z; accp[2] = z; accp[3] = z;
        float ss = 0.f;

        int i = 0;
        for (; i + 4 <= deg; i += 4) {
            int4 sv = *reinterpret_cast<const int4*>(sp + i);
            int sA = g ? sv.y : sv.x;
            int sB = g ? sv.w : sv.z;
            float alA = d_al[sA];
            float alB = d_al[sB];
            uint4 rA = *reinterpret_cast<const uint4*>(hh + (unsigned)sA * HID + ((unsigned)f << 3));
            uint4 rB = *reinterpret_cast<const uint4*>(hh + (unsigned)sB * HID + ((unsigned)f << 3));
            unsigned long long hA[4], hB[4];
            cvt8p(rA, hA); cvt8p(rB, hB);
            unsigned long long dA = mul2(hdp[0], hA[0]);
            unsigned long long dB = mul2(hdp[0], hB[0]);
            dA = fma2(hdp[1], hA[1], dA); dB = fma2(hdp[1], hB[1], dB);
            dA = fma2(hdp[2], hA[2], dA); dB = fma2(hdp[2], hB[2], dB);
            dA = fma2(hdp[3], hA[3], dA); dB = fma2(hdp[3], hB[3], dB);
            float loA, hiA, loB, hiB;
            unpack2(dA, loA, hiA); unpack2(dB, loB, hiB);
            float pA = loA + hiA, pB = loB + hiB;
            #pragma unroll
            for (int off = 8; off; off >>= 1) {
                pA += __shfl_xor_sync(0xffffffffu, pA, off);
                pB += __shfl_xor_sync(0xffffffffu, pB, off);
            }
            float aA = (alA + ard) * (1.0f / (1.0f + __expf(-pA)));
            float aB = (alB + ard) * (1.0f / (1.0f + __expf(-pB)));
            float eA = __expf(aA);
            float eB = __expf(aB);
            unsigned long long eAp = pack2(eA, eA);
            unsigned long long eBp = pack2(eB, eB);
            #pragma unroll
            for (int k = 0; k < 4; k++) {
                accp[k] = fma2(eAp, hA[k], accp[k]);
                accp[k] = fma2(eBp, hB[k], accp[k]);
            }
            ss += eA + eB;
        }
        // tail: 1-3 edges, 2 per step with predication
        for (; i < deg; i += 2) {
            int e0 = i + g;
            bool valid = e0 < deg;
            int s0 = sp[valid ? e0 : 0];
            float al0 = d_al[s0];
            uint4 r0 = *reinterpret_cast<const uint4*>(hh + (unsigned)s0 * HID + ((unsigned)f << 3));
            unsigned long long h0[4];
            cvt8p(r0, h0);
            unsigned long long d0 = mul2(hdp[0], h0[0]);
            d0 = fma2(hdp[1], h0[1], d0);
            d0 = fma2(hdp[2], h0[2], d0);
            d0 = fma2(hdp[3], h0[3], d0);
            float lo, hi;
            unpack2(d0, lo, hi);
            float p0 = lo + hi;
            #pragma unroll
            for (int off = 8; off; off >>= 1) p0 += __shfl_xor_sync(0xffffffffu, p0, off);
            float a0 = (al0 + ard) * (1.0f / (1.0f + __expf(-p0)));
            float e_w = valid ? __expf(a0) : 0.f;
            unsigned long long ep = pack2(e_w, e_w);
            #pragma unroll
            for (int k = 0; k < 4; k++) accp[k] = fma2(ep, h0[k], accp[k]);
            ss += e_w;
        }

        // unpack + combine the two 16-lane groups
        float acc[8];
        unpack2(accp[0], acc[0], acc[1]); unpack2(accp[1], acc[2], acc[3]);
        unpack2(accp[2], acc[4], acc[5]); unpack2(accp[3], acc[6], acc[7]);
        #pragma unroll
        for (int k = 0; k < 8; k++) acc[k] += __shfl_xor_sync(0xffffffffu, acc[k], 16);
        ss += __shfl_xor_sync(0xffffffffu, ss, 16);

        float inv = 1.0f / (ss + 1e-16f);
        float o[8];
        float bv[8] = {bv0.x, bv0.y, bv0.z, bv0.w, bv1.x, bv1.y, bv1.z, bv1.w};
        #pragma unroll
        for (int k = 0; k < 8; k++) {
            o[k] = acc[k] * inv + bv[k];
            if (doRelu) o[k] = fmaxf(o[k], 0.f);
        }

        if (!doProj) {
            float4 st = g ? make_float4(o[4], o[5], o[6], o[7])
                          : make_float4(o[0], o[1], o[2], o[3]);
            *reinterpret_cast<float4*>(d_t1 + rowOff + (g << 2)) = st;
            continue;
        }

        // fused classifier partials: group 0 -> Wc rows 0..127, group 1 -> rows 128..255
        const float* wb = Wc + (g ? 128 * 4 : 0);
        float4 vv = make_float4(0.f, 0.f, 0.f, 0.f);
        #pragma unroll
        for (int k = 0; k < 8; k++) {
            float4 w = *reinterpret_cast<const float4*>(wb + (f * 8 + k) * 4);
            vv.x += o[k] * w.x; vv.y += o[k] * w.y; vv.z += o[k] * w.z; vv.w += o[k] * w.w;
        }
        #pragma unroll
        for (int off = 8; off; off >>= 1) {
            vv.x += __shfl_xor_sync(0xffffffffu, vv.x, off);
            vv.y += __shfl_xor_sync(0xffffffffu, vv.y, off);
            vv.z += __shfl_xor_sync(0xffffffffu, vv.z, off);
            vv.w += __shfl_xor_sync(0xffffffffu, vv.w, off);
        }
        if (f == 0)
            *reinterpret_cast<float4*>(d_p + (unsigned)gw * 8 + (g << 2)) = vv;
    }
}

// ---------------- per-edge output: out[e] = p_src[row] + p_dst[col] + bc ----------------
__global__ void k_edge(const int* __restrict__ ei, const float* __restrict__ bc,
                       float* __restrict__ out) {
    int e = blockIdx.x * blockDim.x + threadIdx.x;
    if (e >= EE) return;
    int r = ei[e], c = ei[EE + e];
    const float4* pv = reinterpret_cast<const float4*>(d_p);
    float4 a = pv[r * 2];
    float4 b = pv[c * 2 + 1];
    float4 bc4 = *reinterpret_cast<const float4*>(bc);
    reinterpret_cast<float4*>(out)[e] =
        make_float4(a.x + b.x + bc4.x, a.y + b.y + bc4.y,
                    a.z + b.z + bc4.z, a.w + b.w + bc4.w);
}

// ---------------- launcher (R9 structure) ----------------
extern "C" void kernel_launch(void* const* d_in, const int* in_sizes, int n_in,
                              void* d_out, int out_size) {
    const float* x   = (const float*)d_in[0];
    const int*   ei  = (const int*)  d_in[1];
    const float* W1  = (const float*)d_in[2];
    const float* al1 = (const float*)d_in[3];
    const float* ar1 = (const float*)d_in[4];
    const float* b1  = (const float*)d_in[5];
    const float* W2  = (const float*)d_in[6];
    const float* al2 = (const float*)d_in[7];
    const float* ar2 = (const float*)d_in[8];
    const float* b2  = (const float*)d_in[9];
    const float* Wc  = (const float*)d_in[10];
    const float* bc  = (const float*)d_in[11];
    float* out = (float*)d_out;

    static cudaStream_t s2 = nullptr;
    static cudaEvent_t evFork = nullptr, evJoin = nullptr;
    if (!s2) {
        cudaStreamCreateWithFlags(&s2, cudaStreamNonBlocking);
        cudaEventCreateWithFlags(&evFork, cudaEventDisableTiming);
        cudaEventCreateWithFlags(&evJoin, cudaEventDisableTiming);
    }

    void* fillPtr = nullptr;
    cudaGetSymbolAddress(&fillPtr, d_fill);

    // fork: bucket build on s2, concurrent with GEMM-1 on the main stream
    cudaEventRecord(evFork, 0);
    cudaStreamWaitEvent(s2, evFork, 0);

    cudaMemsetAsync(fillPtr, 0, NN * sizeof(int), s2);
    k_place1<<<(EE + 255) / 256, 256, 0, s2>>>(ei);                    // kernel #1
    k_place2<<<(NN + 255) / 256, 256, 0, s2>>>();                      // kernel #2
    k_gemm<<<(NN + 127) / 128, 256>>>(x, W1, al1, ar1, 0, 0);          // kernel #3

    cudaEventRecord(evJoin, s2);
    cudaStreamWaitEvent(0, evJoin, 0);

    k_attn<<<ATTN_BLOCKS, 256>>>(0, b1, 1, 0, nullptr);                // kernel #4 <- profiled
    k_gemm<<<(NN + 127) / 128, 256>>>(nullptr, W2, al2, ar2, 1, 1);
    k_attn<<<ATTN_BLOCKS, 256>>>(1, b2, 0, 1, Wc);
    k_edge<<<(EE + 255) / 256, 256>>>(ei, bc, out);
}